// round 15
// baseline (speedup 1.0000x reference)
#include <cuda_runtime.h>
#include <cuda_fp16.h>
#include <math.h>

#define NUSERS 500000
#define MAXN   262144
#define MAXE   4194304
#define MAXEN  (MAXE + MAXN)

// ---------------- scratch (device globals; no allocation allowed) ------------
// feature buffers hold y_l = dinv * x_l (pre-scaled); row n = 64 halfs (128B)
__device__ __half2 g_h0 [MAXN * 32];
__device__ __half2 g_h1 [MAXN * 32];
__device__ __half2 g_h2 [MAXN * 32];
__device__ float   g_dinv [MAXN];
__device__ float   g_loopw[MAXN];
__device__ int     g_s   [MAXN];
__device__ int     g_e   [MAXN];
__device__ int     g_cur [MAXN];
__device__ unsigned long long g_dc[MAXN];  // packed: cnt<<44 | deg*2^20
__device__ int     g_hl  [MAXN + 4];       // hasloop[nn]; [nn]=total, [nn+1]=ni, [nn+2]=nu
__device__ int     g_items[MAXN];
__device__ int     g_users[MAXN];
__device__ int2    g_edge[MAXEN];          // (src, __float_as_int(raw_w))

__device__ __forceinline__ __half2* hbuf(int i) {
    return (i == 0) ? g_h0 : ((i == 1) ? g_h1 : g_h2);
}

// ---------------- kernels ----------------------------------------------------

// no-op: keeps the ncu-profiled 4th-launch slot on k_scatter_feat.
__global__ void k_noop() {}

// slim edge stats: packed deg+cnt atomic + hasloop flag.
__global__ void k_stats(const int* __restrict__ row,
                        const int* __restrict__ col,
                        const float* __restrict__ w, int ee) {
    int e = blockIdx.x * blockDim.x + threadIdx.x;
    if (e >= ee) return;
    int r = row[e], c = col[e];
    if (r == c) g_hl[r] = 1;
    unsigned long long add =
        (1ULL << 44) | (unsigned long long)__float2ull_rn(w[e] * 1048576.0f);
    atomicAdd(&g_dc[c], add);
}

// finalize (loopw/dinv) + CSR region assignment (shuffle scan)
// + partition nodes into item/user lists (warp-aggregated append).
__global__ void k_assign(const int* __restrict__ batch_nodes, int nn) {
    __shared__ int wsum[32];
    __shared__ int base;
    int t = threadIdx.x;
    int lane = t & 31;
    int wid  = t >> 5;
    int i = blockIdx.x * 1024 + t;
    int c = 0;
    bool isit = false;
    if (i < nn) {
        unsigned long long v = g_dc[i];
        float deg = (float)(v & ((1ULL << 44) - 1)) * (1.0f / 1048576.0f);
        int   cnt = (int)(v >> 44);
        float lw = g_hl[i] ? 0.f : 1.f;
        g_loopw[i] = lw;
        float d = deg + lw;
        g_dinv[i] = (d > 0.f) ? rsqrtf(fmaxf(d, 1e-12f)) : 0.f;
        c = cnt + 1;
        isit = (batch_nodes[i] >= NUSERS);
    }
    // ---- item/user list append (warp-aggregated) ----
    unsigned m_it = __ballot_sync(0xffffffffu, isit);
    unsigned m_us = __ballot_sync(0xffffffffu, (i < nn) && !isit);
    int b_it = 0, b_us = 0;
    if (lane == 0) {
        b_it = atomicAdd(&g_hl[nn + 1], __popc(m_it));
        b_us = atomicAdd(&g_hl[nn + 2], __popc(m_us));
    }
    b_it = __shfl_sync(0xffffffffu, b_it, 0);
    b_us = __shfl_sync(0xffffffffu, b_us, 0);
    unsigned below = (1u << lane) - 1;
    if (i < nn) {
        if (isit) g_items[b_it + __popc(m_it & below)] = i;
        else      g_users[b_us + __popc(m_us & below)] = i;
    }
    // ---- CSR scan ----
    int v = c;
    #pragma unroll
    for (int off = 1; off < 32; off <<= 1) {
        int u = __shfl_up_sync(0xffffffffu, v, off);
        if (lane >= off) v += u;
    }
    if (lane == 31) wsum[wid] = v;
    __syncthreads();
    if (wid == 0) {
        int s0 = wsum[lane];
        int sv = s0;
        #pragma unroll
        for (int off = 1; off < 32; off <<= 1) {
            int u = __shfl_up_sync(0xffffffffu, sv, off);
            if (lane >= off) sv += u;
        }
        wsum[lane] = sv - s0;
        if (lane == 31) base = atomicAdd(&g_hl[nn], sv);
    }
    __syncthreads();
    if (i < nn) {
        int incl = v + wsum[wid];
        int start = base + incl - c;
        g_s[i]   = start;
        g_e[i]   = start + c;
        g_cur[i] = start;
    }
}

// three roles:
//   blocks [0, sb):           scatter edges (raw weights)
//   blocks [sb, sb+fi):       item features — 4 items per warp-matvec,
//                             W packed int4 (4×half2 per k4/lane, 1 LDS.128)
//   blocks [sb+fi, sb+fi+fu): user features — streaming copy+normalize
__global__ void __launch_bounds__(256, 6)
k_scatter_feat(const int* __restrict__ row,
               const int* __restrict__ col,
               const float* __restrict__ w,
               const int* __restrict__ batch_nodes,
               const float* __restrict__ user_w,
               const float* __restrict__ artist_w,
               const float* __restrict__ album_w,
               const float* __restrict__ audio,
               const int* __restrict__ artist_ids,
               const int* __restrict__ album_ids,
               const float* __restrict__ proj_w,
               const float* __restrict__ proj_b,
               int ee, int nn, int sb, int fi, int fu) {
    __shared__ int4  Wq[32 * 32];          // 16 KB: Wq[k4*32+l] = 4 half2 (k=4k4..+3, d=2l..2l+1)
    __shared__ float insh[8][4][128];      // 16 KB: 4 staged inputs per warp

    int tid  = threadIdx.x;
    int wid  = tid >> 5;
    int lane = tid & 31;

    if (blockIdx.x < sb) {
        // ----- scatter role -----
        int e = blockIdx.x * blockDim.x + tid;
        if (e >= ee + nn) return;
        int r, tgt;
        float wt;
        if (e < ee) {
            r = row[e]; tgt = col[e]; wt = w[e];
        } else {
            r = tgt = e - ee;
            wt = g_loopw[r];
        }
        int p = atomicAdd(&g_cur[tgt], 1);
        g_edge[p] = make_int2(r, __float_as_int(wt));
        return;
    }

    if (blockIdx.x < sb + fi) {
        // ----- item-feature role -----
        int fbid = blockIdx.x - sb;
        const float2* pw2 = (const float2*)proj_w;
        for (int idx = tid; idx < 1024; idx += 256) {
            int k4 = idx >> 5, l = idx & 31;
            __half2 h0 = __float22half2_rn(pw2[(4*k4 + 0) * 32 + l]);
            __half2 h1 = __float22half2_rn(pw2[(4*k4 + 1) * 32 + l]);
            __half2 h2 = __float22half2_rn(pw2[(4*k4 + 2) * 32 + l]);
            __half2 h3 = __float22half2_rn(pw2[(4*k4 + 3) * 32 + l]);
            int4 v;
            v.x = *(const int*)&h0;  v.y = *(const int*)&h1;
            v.z = *(const int*)&h2;  v.w = *(const int*)&h3;
            Wq[idx] = v;
        }
        __syncthreads();

        const float2* audio2  = (const float2*)audio;
        const float2* artist2 = (const float2*)artist_w;
        const float2* album2  = (const float2*)album_w;
        const float2* pb2     = (const float2*)proj_b;

        int ni = g_hl[nn + 1];
        int nb = (ni + 3) >> 2;
        for (int cb = fbid * 8 + wid; cb < nb; cb += fi * 8) {
            int ids[4];
            #pragma unroll
            for (int j = 0; j < 4; j++) {
                int slot = cb * 4 + j;
                ids[j] = g_items[slot < ni ? slot : cb * 4];
            }
            #pragma unroll
            for (int j = 0; j < 4; j++) {
                int it  = batch_nodes[ids[j]] - NUSERS;
                float2 au = audio2[(size_t)it * 32 + lane];
                int aid = artist_ids[it];
                int bid = album_ids[it];
                float2 ar = artist2[(size_t)aid * 32 + lane];
                float2 al = album2[(size_t)bid * 32 + lane];
                float2* rowp = (float2*)insh[wid][j];
                rowp[lane]      = au;
                rowp[32 + lane] = make_float2(0.5f * (ar.x + al.x),
                                              0.5f * (ar.y + al.y));
            }
            __syncwarp();
            float2 pb = pb2[lane];
            float2 s0 = pb, s1 = pb, s2 = pb, s3 = pb;
            const float4* i0 = (const float4*)insh[wid][0];
            const float4* i1 = (const float4*)insh[wid][1];
            const float4* i2 = (const float4*)insh[wid][2];
            const float4* i3 = (const float4*)insh[wid][3];
            #pragma unroll 4
            for (int k4 = 0; k4 < 32; k4++) {
                int4 wv = Wq[k4 * 32 + lane];      // one LDS.128 for 4 k's
                const __half2* wh = (const __half2*)&wv;
                float2 w0 = __half22float2(wh[0]);
                float2 w1 = __half22float2(wh[1]);
                float2 w2 = __half22float2(wh[2]);
                float2 w3 = __half22float2(wh[3]);
                float4 v0 = i0[k4], v1 = i1[k4], v2 = i2[k4], v3 = i3[k4];
                s0.x += v0.x*w0.x + v0.y*w1.x + v0.z*w2.x + v0.w*w3.x;
                s0.y += v0.x*w0.y + v0.y*w1.y + v0.z*w2.y + v0.w*w3.y;
                s1.x += v1.x*w0.x + v1.y*w1.x + v1.z*w2.x + v1.w*w3.x;
                s1.y += v1.x*w0.y + v1.y*w1.y + v1.z*w2.y + v1.w*w3.y;
                s2.x += v2.x*w0.x + v2.y*w1.x + v2.z*w2.x + v2.w*w3.x;
                s2.y += v2.x*w0.y + v2.y*w1.y + v2.z*w2.y + v2.w*w3.y;
                s3.x += v3.x*w0.x + v3.y*w1.x + v3.z*w2.x + v3.w*w3.x;
                s3.y += v3.x*w0.y + v3.y*w1.y + v3.z*w2.y + v3.w*w3.y;
            }
            __syncwarp();
            #pragma unroll
            for (int j = 0; j < 4; j++) {
                if (cb * 4 + j >= ni) break;
                float2 o = (j == 0) ? s0 : (j == 1) ? s1 : (j == 2) ? s2 : s3;
                float ss = o.x * o.x + o.y * o.y;
                #pragma unroll
                for (int off = 16; off; off >>= 1)
                    ss += __shfl_xor_sync(0xffffffffu, ss, off);
                int n = ids[j];
                float inv = g_dinv[n] / fmaxf(sqrtf(ss), 1e-12f);
                g_h0[(size_t)n * 32 + lane] =
                    __float22half2_rn(make_float2(o.x * inv, o.y * inv));
            }
        }
        return;
    }

    // ----- user-feature role -----
    {
        int ubid = blockIdx.x - sb - fi;
        const float2* user2 = (const float2*)user_w;
        int nu = g_hl[nn + 2];
        for (int u = ubid * 8 + wid; u < nu; u += fu * 8) {
            int n  = g_users[u];
            int bn = batch_nodes[n];
            float2 o = user2[(size_t)bn * 32 + lane];
            float ss = o.x * o.x + o.y * o.y;
            #pragma unroll
            for (int off = 16; off; off >>= 1)
                ss += __shfl_xor_sync(0xffffffffu, ss, off);
            float inv = g_dinv[n] / fmaxf(sqrtf(ss), 1e-12f);
            g_h0[(size_t)n * 32 + lane] =
                __float22half2_rn(make_float2(o.x * inv, o.y * inv));
        }
    }
}

// prop v5 with factored normalization: buffers hold y = dinv*x.
// acc[c] = sum_e w_e * y[r];  y_new[c] = dinv[c]^2 * acc.
// last!=0: out = l2norm(y0+y1+y2+dinv^2*acc)  (l2norm is scale-invariant).
__global__ void k_prop4(int si, int so, int last, int nn,
                        float2* __restrict__ out) {
    const __half2* __restrict__ xin = hbuf(si);
    int g = blockIdx.x * blockDim.x + threadIdx.x;
    int warp = g >> 5;
    int lane = threadIdx.x & 31;
    int grp  = lane >> 3;     // node slot within warp
    int li   = lane & 7;      // lane within node (dims 8li..8li+7)
    int n = warp * 4 + grp;
    bool valid = (n < nn);

    int s = 0, deg = 0;
    if (valid) { s = g_s[n]; deg = g_e[n] - s; }
    int maxdeg = (int)__reduce_max_sync(0xffffffffu, (unsigned)deg);

    float4 a0 = make_float4(0.f, 0.f, 0.f, 0.f);
    float4 a1 = make_float4(0.f, 0.f, 0.f, 0.f);

    for (int off = 0; off < maxdeg; off += 8) {
        int2 ed = make_int2(0, 0);                 // w = 0.0f padding
        if (off + li < deg) ed = g_edge[s + off + li];
        int jc = maxdeg - off; if (jc > 8) jc = 8;
        #pragma unroll 2
        for (int j = 0; j < jc; j++) {
            int src = grp * 8 + j;
            int   r = __shfl_sync(0xffffffffu, ed.x, src);
            float wgt = __int_as_float(__shfl_sync(0xffffffffu, ed.y, src));
            int4 hv = ((const int4*)(xin + (size_t)r * 32))[li];
            const __half2* hp = (const __half2*)&hv;
            float2 f0 = __half22float2(hp[0]);
            float2 f1 = __half22float2(hp[1]);
            float2 f2 = __half22float2(hp[2]);
            float2 f3 = __half22float2(hp[3]);
            a0.x += wgt * f0.x;  a0.y += wgt * f0.y;
            a0.z += wgt * f1.x;  a0.w += wgt * f1.y;
            a1.x += wgt * f2.x;  a1.y += wgt * f2.y;
            a1.z += wgt * f3.x;  a1.w += wgt * f3.y;
        }
    }

    if (!valid) return;

    float dv  = g_dinv[n];
    float dv2 = dv * dv;

    if (!last) {
        __half2 o0 = __float22half2_rn(make_float2(a0.x * dv2, a0.y * dv2));
        __half2 o1 = __float22half2_rn(make_float2(a0.z * dv2, a0.w * dv2));
        __half2 o2 = __float22half2_rn(make_float2(a1.x * dv2, a1.y * dv2));
        __half2 o3 = __float22half2_rn(make_float2(a1.z * dv2, a1.w * dv2));
        int4 v;
        v.x = *(const int*)&o0;  v.y = *(const int*)&o1;
        v.z = *(const int*)&o2;  v.w = *(const int*)&o3;
        ((int4*)(hbuf(so) + (size_t)n * 32))[li] = v;
    } else {
        int4 h0v = ((const int4*)(g_h0 + (size_t)n * 32))[li];
        int4 h1v = ((const int4*)(g_h1 + (size_t)n * 32))[li];
        int4 h2v = ((const int4*)(xin  + (size_t)n * 32))[li];  // xin == g_h2
        const __half2* p0 = (const __half2*)&h0v;
        const __half2* p1 = (const __half2*)&h1v;
        const __half2* p2 = (const __half2*)&h2v;
        float f[8] = {a0.x, a0.y, a0.z, a0.w, a1.x, a1.y, a1.z, a1.w};
        #pragma unroll
        for (int q = 0; q < 4; q++) {
            float2 y0 = __half22float2(p0[q]);
            float2 y1 = __half22float2(p1[q]);
            float2 y2 = __half22float2(p2[q]);
            f[2*q]   = y0.x + y1.x + y2.x + dv2 * f[2*q];
            f[2*q+1] = y0.y + y1.y + y2.y + dv2 * f[2*q+1];
        }
        float ss = 0.f;
        #pragma unroll
        for (int q = 0; q < 8; q++) ss += f[q] * f[q];
        #pragma unroll
        for (int off = 1; off <= 4; off <<= 1)
            ss += __shfl_xor_sync(0xffffffffu, ss, off);
        float inv = 1.0f / fmaxf(sqrtf(ss), 1e-12f);
        float4 w0 = make_float4(f[0]*inv, f[1]*inv, f[2]*inv, f[3]*inv);
        float4 w1 = make_float4(f[4]*inv, f[5]*inv, f[6]*inv, f[7]*inv);
        float4* orow = (float4*)(out + (size_t)n * 32);
        orow[li * 2]     = w0;
        orow[li * 2 + 1] = w1;
    }
}

// ---------------- launch -----------------------------------------------------

extern "C" void kernel_launch(void* const* d_in, const int* in_sizes, int n_in,
                              void* d_out, int out_size) {
    const int*   batch_nodes = (const int*)  d_in[0];
    const int*   edge_index  = (const int*)  d_in[1];
    const float* edge_w      = (const float*)d_in[2];
    const float* user_w      = (const float*)d_in[3];
    const float* artist_w    = (const float*)d_in[4];
    const float* album_w     = (const float*)d_in[5];
    const float* audio       = (const float*)d_in[6];
    const int*   artist_ids  = (const int*)  d_in[7];
    const int*   album_ids   = (const int*)  d_in[8];
    const float* proj_w      = (const float*)d_in[9];
    const float* proj_b      = (const float*)d_in[10];
    float2*      out         = (float2*)d_out;

    const int nn = in_sizes[0];
    const int ee = in_sizes[2];
    const int* row = edge_index;
    const int* col = edge_index + (in_sizes[1] - ee);

    void* p1 = nullptr; void* p2 = nullptr;
    cudaGetSymbolAddress(&p1, g_dc);
    cudaGetSymbolAddress(&p2, g_hl);
    cudaMemsetAsync(p1, 0, (size_t)nn * sizeof(unsigned long long));
    cudaMemsetAsync(p2, 0, (size_t)(nn + 3) * sizeof(int));

    k_noop  <<<1, 32>>>();                                 // keeps profile slot
    k_stats <<<(ee + 255) / 256, 256>>>(row, col, edge_w, ee);
    k_assign<<<(nn + 1023) / 1024, 1024>>>(batch_nodes, nn);

    const int sb = (ee + nn + 255) / 256;     // scatter role blocks
    const int fi = 1024;                      // item-feature role blocks
    const int fu = 512;                       // user-feature role blocks
    k_scatter_feat<<<sb + fi + fu, 256>>>(row, col, edge_w, batch_nodes,
                                          user_w, artist_w, album_w, audio,
                                          artist_ids, album_ids, proj_w, proj_b,
                                          ee, nn, sb, fi, fu);  // profiled (4th)

    const int prop4_blocks = (nn * 8 + 255) / 256;         // 4 nodes/warp
    k_prop4<<<prop4_blocks, 256>>>(0, 1, 0, nn, out);      // layer 1
    k_prop4<<<prop4_blocks, 256>>>(1, 2, 0, nn, out);      // layer 2
    k_prop4<<<prop4_blocks, 256>>>(2, 0, 1, nn, out);      // layer 3 + finale
}

// round 16
// speedup vs baseline: 1.0497x; 1.0497x over previous
#include <cuda_runtime.h>
#include <cuda_fp16.h>
#include <math.h>

#define NUSERS 500000
#define MAXN   262144
#define MAXE   4194304
#define MAXEN  (MAXE + MAXN)

// ---------------- scratch (device globals; no allocation allowed) ------------
// feature buffers hold y_l = dinv * x_l (pre-scaled); row n = 64 halfs (128B)
__device__ __half2 g_h0 [MAXN * 32];
__device__ __half2 g_h1 [MAXN * 32];
__device__ __half2 g_h2 [MAXN * 32];
__device__ float   g_dinv [MAXN];
__device__ float   g_loopw[MAXN];
__device__ int     g_s   [MAXN];
__device__ int     g_e   [MAXN];
__device__ unsigned long long g_dc[MAXN];  // packed: cnt<<44 | deg*2^20
__device__ int     g_hl  [MAXN + 4];       // hasloop[nn]; [nn]=total, [nn+1]=ni, [nn+2]=nu
__device__ int     g_items[MAXN];
__device__ int     g_users[MAXN];
__device__ int     g_rank[MAXE];           // per-edge rank within its column
__device__ int2    g_edge[MAXEN];          // (src, __float_as_int(raw_w))

__device__ __forceinline__ __half2* hbuf(int i) {
    return (i == 0) ? g_h0 : ((i == 1) ? g_h1 : g_h2);
}

// ---------------- kernels ----------------------------------------------------

// no-op: keeps the ncu-profiled 4th-launch slot on k_scatter_feat.
__global__ void k_noop() {}

// edge stats: packed deg+cnt atomic. The returned old cnt is this edge's
// rank within its destination column -> persisted for atomic-free scatter.
__global__ void k_stats(const int* __restrict__ row,
                        const int* __restrict__ col,
                        const float* __restrict__ w, int ee) {
    int e = blockIdx.x * blockDim.x + threadIdx.x;
    if (e >= ee) return;
    int r = row[e], c = col[e];
    if (r == c) g_hl[r] = 1;
    unsigned long long add =
        (1ULL << 44) | (unsigned long long)__float2ull_rn(w[e] * 1048576.0f);
    unsigned long long old = atomicAdd(&g_dc[c], add);
    g_rank[e] = (int)(old >> 44);
}

// finalize (loopw/dinv) + CSR region assignment (shuffle scan)
// + partition nodes into item/user lists (warp-aggregated append).
__global__ void k_assign(const int* __restrict__ batch_nodes, int nn) {
    __shared__ int wsum[32];
    __shared__ int base;
    int t = threadIdx.x;
    int lane = t & 31;
    int wid  = t >> 5;
    int i = blockIdx.x * 1024 + t;
    int c = 0;
    bool isit = false;
    if (i < nn) {
        unsigned long long v = g_dc[i];
        float deg = (float)(v & ((1ULL << 44) - 1)) * (1.0f / 1048576.0f);
        int   cnt = (int)(v >> 44);
        float lw = g_hl[i] ? 0.f : 1.f;
        g_loopw[i] = lw;
        float d = deg + lw;
        g_dinv[i] = (d > 0.f) ? rsqrtf(fmaxf(d, 1e-12f)) : 0.f;
        c = cnt + 1;
        isit = (batch_nodes[i] >= NUSERS);
    }
    // ---- item/user list append (warp-aggregated) ----
    unsigned m_it = __ballot_sync(0xffffffffu, isit);
    unsigned m_us = __ballot_sync(0xffffffffu, (i < nn) && !isit);
    int b_it = 0, b_us = 0;
    if (lane == 0) {
        b_it = atomicAdd(&g_hl[nn + 1], __popc(m_it));
        b_us = atomicAdd(&g_hl[nn + 2], __popc(m_us));
    }
    b_it = __shfl_sync(0xffffffffu, b_it, 0);
    b_us = __shfl_sync(0xffffffffu, b_us, 0);
    unsigned below = (1u << lane) - 1;
    if (i < nn) {
        if (isit) g_items[b_it + __popc(m_it & below)] = i;
        else      g_users[b_us + __popc(m_us & below)] = i;
    }
    // ---- CSR scan ----
    int v = c;
    #pragma unroll
    for (int off = 1; off < 32; off <<= 1) {
        int u = __shfl_up_sync(0xffffffffu, v, off);
        if (lane >= off) v += u;
    }
    if (lane == 31) wsum[wid] = v;
    __syncthreads();
    if (wid == 0) {
        int s0 = wsum[lane];
        int sv = s0;
        #pragma unroll
        for (int off = 1; off < 32; off <<= 1) {
            int u = __shfl_up_sync(0xffffffffu, sv, off);
            if (lane >= off) sv += u;
        }
        wsum[lane] = sv - s0;
        if (lane == 31) base = atomicAdd(&g_hl[nn], sv);
    }
    __syncthreads();
    if (i < nn) {
        int incl = v + wsum[wid];
        int start = base + incl - c;
        g_s[i] = start;
        g_e[i] = start + c;
    }
}

// three roles (features FIRST so their latency chains overlap the scatter flood):
//   blocks [0, fi):            item features — 4 items per warp-matvec
//   blocks [fi, fi+fu):        user features — streaming copy+normalize
//   blocks [fi+fu, fi+fu+sb):  scatter edges at deterministic slots (NO atomics)
__global__ void __launch_bounds__(256, 6)
k_scatter_feat(const int* __restrict__ row,
               const int* __restrict__ col,
               const float* __restrict__ w,
               const int* __restrict__ batch_nodes,
               const float* __restrict__ user_w,
               const float* __restrict__ artist_w,
               const float* __restrict__ album_w,
               const float* __restrict__ audio,
               const int* __restrict__ artist_ids,
               const int* __restrict__ album_ids,
               const float* __restrict__ proj_w,
               const float* __restrict__ proj_b,
               int ee, int nn, int sb, int fi, int fu) {
    __shared__ int4  Wq[32 * 32];          // 16 KB: 4 half2 per (k4, lane)
    __shared__ float insh[8][4][128];      // 16 KB: 4 staged inputs per warp

    int tid  = threadIdx.x;
    int wid  = tid >> 5;
    int lane = tid & 31;

    if (blockIdx.x < fi) {
        // ----- item-feature role -----
        int fbid = blockIdx.x;
        const float2* pw2 = (const float2*)proj_w;
        for (int idx = tid; idx < 1024; idx += 256) {
            int k4 = idx >> 5, l = idx & 31;
            __half2 h0 = __float22half2_rn(pw2[(4*k4 + 0) * 32 + l]);
            __half2 h1 = __float22half2_rn(pw2[(4*k4 + 1) * 32 + l]);
            __half2 h2 = __float22half2_rn(pw2[(4*k4 + 2) * 32 + l]);
            __half2 h3 = __float22half2_rn(pw2[(4*k4 + 3) * 32 + l]);
            int4 v;
            v.x = *(const int*)&h0;  v.y = *(const int*)&h1;
            v.z = *(const int*)&h2;  v.w = *(const int*)&h3;
            Wq[idx] = v;
        }
        __syncthreads();

        const float2* audio2  = (const float2*)audio;
        const float2* artist2 = (const float2*)artist_w;
        const float2* album2  = (const float2*)album_w;
        const float2* pb2     = (const float2*)proj_b;

        int ni = g_hl[nn + 1];
        int nb = (ni + 3) >> 2;
        for (int cb = fbid * 8 + wid; cb < nb; cb += fi * 8) {
            int ids[4];
            #pragma unroll
            for (int j = 0; j < 4; j++) {
                int slot = cb * 4 + j;
                ids[j] = g_items[slot < ni ? slot : cb * 4];
            }
            #pragma unroll
            for (int j = 0; j < 4; j++) {
                int it  = batch_nodes[ids[j]] - NUSERS;
                float2 au = audio2[(size_t)it * 32 + lane];
                int aid = artist_ids[it];
                int bid = album_ids[it];
                float2 ar = artist2[(size_t)aid * 32 + lane];
                float2 al = album2[(size_t)bid * 32 + lane];
                float2* rowp = (float2*)insh[wid][j];
                rowp[lane]      = au;
                rowp[32 + lane] = make_float2(0.5f * (ar.x + al.x),
                                              0.5f * (ar.y + al.y));
            }
            __syncwarp();
            float2 pb = pb2[lane];
            float2 s0 = pb, s1 = pb, s2 = pb, s3 = pb;
            const float4* i0 = (const float4*)insh[wid][0];
            const float4* i1 = (const float4*)insh[wid][1];
            const float4* i2 = (const float4*)insh[wid][2];
            const float4* i3 = (const float4*)insh[wid][3];
            #pragma unroll 4
            for (int k4 = 0; k4 < 32; k4++) {
                int4 wv = Wq[k4 * 32 + lane];      // one LDS.128 for 4 k's
                const __half2* wh = (const __half2*)&wv;
                float2 w0 = __half22float2(wh[0]);
                float2 w1 = __half22float2(wh[1]);
                float2 w2 = __half22float2(wh[2]);
                float2 w3 = __half22float2(wh[3]);
                float4 v0 = i0[k4], v1 = i1[k4], v2 = i2[k4], v3 = i3[k4];
                s0.x += v0.x*w0.x + v0.y*w1.x + v0.z*w2.x + v0.w*w3.x;
                s0.y += v0.x*w0.y + v0.y*w1.y + v0.z*w2.y + v0.w*w3.y;
                s1.x += v1.x*w0.x + v1.y*w1.x + v1.z*w2.x + v1.w*w3.x;
                s1.y += v1.x*w0.y + v1.y*w1.y + v1.z*w2.y + v1.w*w3.y;
                s2.x += v2.x*w0.x + v2.y*w1.x + v2.z*w2.x + v2.w*w3.x;
                s2.y += v2.x*w0.y + v2.y*w1.y + v2.z*w2.y + v2.w*w3.y;
                s3.x += v3.x*w0.x + v3.y*w1.x + v3.z*w2.x + v3.w*w3.x;
                s3.y += v3.x*w0.y + v3.y*w1.y + v3.z*w2.y + v3.w*w3.y;
            }
            __syncwarp();
            #pragma unroll
            for (int j = 0; j < 4; j++) {
                if (cb * 4 + j >= ni) break;
                float2 o = (j == 0) ? s0 : (j == 1) ? s1 : (j == 2) ? s2 : s3;
                float ss = o.x * o.x + o.y * o.y;
                #pragma unroll
                for (int off = 16; off; off >>= 1)
                    ss += __shfl_xor_sync(0xffffffffu, ss, off);
                int n = ids[j];
                float inv = g_dinv[n] / fmaxf(sqrtf(ss), 1e-12f);
                g_h0[(size_t)n * 32 + lane] =
                    __float22half2_rn(make_float2(o.x * inv, o.y * inv));
            }
        }
        return;
    }

    if (blockIdx.x < fi + fu) {
        // ----- user-feature role -----
        int ubid = blockIdx.x - fi;
        const float2* user2 = (const float2*)user_w;
        int nu = g_hl[nn + 2];
        for (int u = ubid * 8 + wid; u < nu; u += fu * 8) {
            int n  = g_users[u];
            int bn = batch_nodes[n];
            float2 o = user2[(size_t)bn * 32 + lane];
            float ss = o.x * o.x + o.y * o.y;
            #pragma unroll
            for (int off = 16; off; off >>= 1)
                ss += __shfl_xor_sync(0xffffffffu, ss, off);
            float inv = g_dinv[n] / fmaxf(sqrtf(ss), 1e-12f);
            g_h0[(size_t)n * 32 + lane] =
                __float22half2_rn(make_float2(o.x * inv, o.y * inv));
        }
        return;
    }

    // ----- scatter role: deterministic slots, NO atomics -----
    {
        int e = (blockIdx.x - fi - fu) * blockDim.x + tid;
        if (e >= ee + nn) return;
        if (e < ee) {
            int c = col[e];
            int pos = g_s[c] + g_rank[e];
            g_edge[pos] = make_int2(row[e], __float_as_int(w[e]));
        } else {
            int i = e - ee;
            g_edge[g_e[i] - 1] = make_int2(i, __float_as_int(g_loopw[i]));
        }
    }
}

// prop v5 with factored normalization: buffers hold y = dinv*x.
// acc[c] = sum_e w_e * y[r];  y_new[c] = dinv[c]^2 * acc.
// last!=0: out = l2norm(y0+y1+y2+dinv^2*acc)  (l2norm is scale-invariant).
__global__ void k_prop4(int si, int so, int last, int nn,
                        float2* __restrict__ out) {
    const __half2* __restrict__ xin = hbuf(si);
    int g = blockIdx.x * blockDim.x + threadIdx.x;
    int warp = g >> 5;
    int lane = threadIdx.x & 31;
    int grp  = lane >> 3;     // node slot within warp
    int li   = lane & 7;      // lane within node (dims 8li..8li+7)
    int n = warp * 4 + grp;
    bool valid = (n < nn);

    int s = 0, deg = 0;
    if (valid) { s = g_s[n]; deg = g_e[n] - s; }
    int maxdeg = (int)__reduce_max_sync(0xffffffffu, (unsigned)deg);

    float4 a0 = make_float4(0.f, 0.f, 0.f, 0.f);
    float4 a1 = make_float4(0.f, 0.f, 0.f, 0.f);

    for (int off = 0; off < maxdeg; off += 8) {
        int2 ed = make_int2(0, 0);                 // w = 0.0f padding
        if (off + li < deg) ed = g_edge[s + off + li];
        int jc = maxdeg - off; if (jc > 8) jc = 8;
        #pragma unroll 2
        for (int j = 0; j < jc; j++) {
            int src = grp * 8 + j;
            int   r = __shfl_sync(0xffffffffu, ed.x, src);
            float wgt = __int_as_float(__shfl_sync(0xffffffffu, ed.y, src));
            int4 hv = ((const int4*)(xin + (size_t)r * 32))[li];
            const __half2* hp = (const __half2*)&hv;
            float2 f0 = __half22float2(hp[0]);
            float2 f1 = __half22float2(hp[1]);
            float2 f2 = __half22float2(hp[2]);
            float2 f3 = __half22float2(hp[3]);
            a0.x += wgt * f0.x;  a0.y += wgt * f0.y;
            a0.z += wgt * f1.x;  a0.w += wgt * f1.y;
            a1.x += wgt * f2.x;  a1.y += wgt * f2.y;
            a1.z += wgt * f3.x;  a1.w += wgt * f3.y;
        }
    }

    if (!valid) return;

    float dv  = g_dinv[n];
    float dv2 = dv * dv;

    if (!last) {
        __half2 o0 = __float22half2_rn(make_float2(a0.x * dv2, a0.y * dv2));
        __half2 o1 = __float22half2_rn(make_float2(a0.z * dv2, a0.w * dv2));
        __half2 o2 = __float22half2_rn(make_float2(a1.x * dv2, a1.y * dv2));
        __half2 o3 = __float22half2_rn(make_float2(a1.z * dv2, a1.w * dv2));
        int4 v;
        v.x = *(const int*)&o0;  v.y = *(const int*)&o1;
        v.z = *(const int*)&o2;  v.w = *(const int*)&o3;
        ((int4*)(hbuf(so) + (size_t)n * 32))[li] = v;
    } else {
        int4 h0v = ((const int4*)(g_h0 + (size_t)n * 32))[li];
        int4 h1v = ((const int4*)(g_h1 + (size_t)n * 32))[li];
        int4 h2v = ((const int4*)(xin  + (size_t)n * 32))[li];  // xin == g_h2
        const __half2* p0 = (const __half2*)&h0v;
        const __half2* p1 = (const __half2*)&h1v;
        const __half2* p2 = (const __half2*)&h2v;
        float f[8] = {a0.x, a0.y, a0.z, a0.w, a1.x, a1.y, a1.z, a1.w};
        #pragma unroll
        for (int q = 0; q < 4; q++) {
            float2 y0 = __half22float2(p0[q]);
            float2 y1 = __half22float2(p1[q]);
            float2 y2 = __half22float2(p2[q]);
            f[2*q]   = y0.x + y1.x + y2.x + dv2 * f[2*q];
            f[2*q+1] = y0.y + y1.y + y2.y + dv2 * f[2*q+1];
        }
        float ss = 0.f;
        #pragma unroll
        for (int q = 0; q < 8; q++) ss += f[q] * f[q];
        #pragma unroll
        for (int off = 1; off <= 4; off <<= 1)
            ss += __shfl_xor_sync(0xffffffffu, ss, off);
        float inv = 1.0f / fmaxf(sqrtf(ss), 1e-12f);
        float4 w0 = make_float4(f[0]*inv, f[1]*inv, f[2]*inv, f[3]*inv);
        float4 w1 = make_float4(f[4]*inv, f[5]*inv, f[6]*inv, f[7]*inv);
        float4* orow = (float4*)(out + (size_t)n * 32);
        orow[li * 2]     = w0;
        orow[li * 2 + 1] = w1;
    }
}

// ---------------- launch -----------------------------------------------------

extern "C" void kernel_launch(void* const* d_in, const int* in_sizes, int n_in,
                              void* d_out, int out_size) {
    const int*   batch_nodes = (const int*)  d_in[0];
    const int*   edge_index  = (const int*)  d_in[1];
    const float* edge_w      = (const float*)d_in[2];
    const float* user_w      = (const float*)d_in[3];
    const float* artist_w    = (const float*)d_in[4];
    const float* album_w     = (const float*)d_in[5];
    const float* audio       = (const float*)d_in[6];
    const int*   artist_ids  = (const int*)  d_in[7];
    const int*   album_ids   = (const int*)  d_in[8];
    const float* proj_w      = (const float*)d_in[9];
    const float* proj_b      = (const float*)d_in[10];
    float2*      out         = (float2*)d_out;

    const int nn = in_sizes[0];
    const int ee = in_sizes[2];
    const int* row = edge_index;
    const int* col = edge_index + (in_sizes[1] - ee);

    void* p1 = nullptr; void* p2 = nullptr;
    cudaGetSymbolAddress(&p1, g_dc);
    cudaGetSymbolAddress(&p2, g_hl);
    cudaMemsetAsync(p1, 0, (size_t)nn * sizeof(unsigned long long));
    cudaMemsetAsync(p2, 0, (size_t)(nn + 3) * sizeof(int));

    k_noop  <<<1, 32>>>();                                 // keeps profile slot
    k_stats <<<(ee + 255) / 256, 256>>>(row, col, edge_w, ee);
    k_assign<<<(nn + 1023) / 1024, 1024>>>(batch_nodes, nn);

    const int sb = (ee + nn + 255) / 256;     // scatter role blocks
    const int fi = 1024;                      // item-feature role blocks
    const int fu = 512;                       // user-feature role blocks
    k_scatter_feat<<<sb + fi + fu, 256>>>(row, col, edge_w, batch_nodes,
                                          user_w, artist_w, album_w, audio,
                                          artist_ids, album_ids, proj_w, proj_b,
                                          ee, nn, sb, fi, fu);  // profiled (4th)

    const int prop4_blocks = (nn * 8 + 255) / 256;         // 4 nodes/warp
    k_prop4<<<prop4_blocks, 256>>>(0, 1, 0, nn, out);      // layer 1
    k_prop4<<<prop4_blocks, 256>>>(1, 2, 0, nn, out);      // layer 2
    k_prop4<<<prop4_blocks, 256>>>(2, 0, 1, nn, out);      // layer 3 + finale
}